// round 4
// baseline (speedup 1.0000x reference)
#include <cuda_runtime.h>
#include <cstdint>

// VecArrayMultiplier54x54: the {0,1} gate network is exact, so
// out[row] = bits of (uint54(A[row]) * uint54(B[row])), LSB first, as 0/1 floats.
//
// R4 = R3 dataflow (1 row/warp: 4 coalesced LDG.32 -> 4 ballots -> 64x64->128
// IMAD -> lane<27 STG.128 of bit-pattern floats), but 512 threads/block so the
// grid is 512 CTAs instead of 1024 (same 8192 resident warps, regs=16).
// Targets the CTA launch-ramp term, the last unexplained component of the
// 5us cold / 6.88us e2e floor.

__global__ void __launch_bounds__(512)
mul54x54_kernel(const float* __restrict__ A,
                const float* __restrict__ B,
                float* __restrict__ out,
                int batch) {
    const int row  = (int)((blockIdx.x * blockDim.x + threadIdx.x) >> 5);
    const int lane = threadIdx.x & 31;
    if (row >= batch) return;

    const float* __restrict__ a_row = A + (size_t)row * 54;
    const float* __restrict__ b_row = B + (size_t)row * 54;

    // Front-batched independent loads (MLP=4 per thread, fully coalesced).
    float av0 = a_row[lane];
    float bv0 = b_row[lane];
    float av1 = 0.0f, bv1 = 0.0f;
    if (lane < 22) {
        av1 = a_row[32 + lane];
        bv1 = b_row[32 + lane];
    }

    unsigned ma0 = __ballot_sync(0xFFFFFFFFu, av0 > 0.5f);
    unsigned ma1 = __ballot_sync(0xFFFFFFFFu, av1 > 0.5f);
    unsigned mb0 = __ballot_sync(0xFFFFFFFFu, bv0 > 0.5f);
    unsigned mb1 = __ballot_sync(0xFFFFFFFFu, bv1 > 0.5f);

    const uint64_t a = (uint64_t)ma0 | ((uint64_t)(ma1 & 0x3FFFFFu) << 32);
    const uint64_t b = (uint64_t)mb0 | ((uint64_t)(mb1 & 0x3FFFFFu) << 32);

    const uint64_t lo = a * b;             // product bits [0:64)
    const uint64_t hi = __umul64hi(a, b);  // product bits [64:108)

    if (lane < 27) {
        // Nibble 4*lane .. 4*lane+3 of the 108-bit product -> 4 floats -> STG.128.
        unsigned nib = (lane < 16) ? (unsigned)(lo >> (lane * 4))
                                   : (unsigned)(hi >> ((lane - 16) * 4));
        uint4 v;
        v.x = ( nib        & 1u) * 0x3F800000u;
        v.y = ((nib >> 1)  & 1u) * 0x3F800000u;
        v.z = ((nib >> 2)  & 1u) * 0x3F800000u;
        v.w = ((nib >> 3)  & 1u) * 0x3F800000u;
        ((uint4*)(out + (size_t)row * 108))[lane] = v;
    }
}

extern "C" void kernel_launch(void* const* d_in, const int* in_sizes, int n_in,
                              void* d_out, int out_size) {
    const float* A = (const float*)d_in[0];
    const float* B = (const float*)d_in[1];
    float* out = (float*)d_out;

    const int batch = in_sizes[0] / 54;          // 8192 expected
    const int threads = 512;                     // 16 warps/block -> 512 CTAs
    const int warpsPerBlock = threads / 32;
    const int blocks = (batch + warpsPerBlock - 1) / warpsPerBlock;

    mul54x54_kernel<<<blocks, threads>>>(A, B, out, batch);
}

// round 5
// speedup vs baseline: 1.0386x; 1.0386x over previous
#include <cuda_runtime.h>
#include <cstdint>

// VecArrayMultiplier54x54: the {0,1} gate network is exact, so
// out[row] = bits of (uint54(A[row]) * uint54(B[row])), LSB first, as 0/1 floats.
//
// R5: 4 rows per warp, ALL 16 loads front-batched (MLP=16 per thread-slot)
// to amortize the cold-DRAM round trip that dominates the profiled duration.
// Row r_i = gwarp + i*NW keeps adjacent warps on adjacent rows (coalesced).
// Epilogue per row: 4 ballots -> 64x64->128 IMAD -> lane<27 STG.128 of
// bit-pattern floats (bit * 0x3F800000, no I2F).

#define ROWS_PER_WARP 4

__global__ void __launch_bounds__(256)
mul54x54_mlp_kernel(const float* __restrict__ A,
                    const float* __restrict__ B,
                    float* __restrict__ out,
                    int batch) {
    const int gwarp = (int)((blockIdx.x * blockDim.x + threadIdx.x) >> 5);
    const int lane  = threadIdx.x & 31;
    const int nwarps = (int)(gridDim.x * blockDim.x) >> 5;

    int rows[ROWS_PER_WARP];
    float av0[ROWS_PER_WARP], bv0[ROWS_PER_WARP];
    float av1[ROWS_PER_WARP], bv1[ROWS_PER_WARP];

    const bool tail = (lane < 22);

    // Front-batched loads: 16 independent LDG.32 before any dependency.
    #pragma unroll
    for (int i = 0; i < ROWS_PER_WARP; i++) {
        int row = gwarp + i * nwarps;
        rows[i] = row;
        av1[i] = 0.0f; bv1[i] = 0.0f;
        if (row < batch) {
            const float* __restrict__ a_row = A + (size_t)row * 54;
            const float* __restrict__ b_row = B + (size_t)row * 54;
            av0[i] = a_row[lane];
            bv0[i] = b_row[lane];
            if (tail) {
                av1[i] = a_row[32 + lane];
                bv1[i] = b_row[32 + lane];
            }
        } else {
            av0[i] = 0.0f; bv0[i] = 0.0f;
        }
    }

    #pragma unroll
    for (int i = 0; i < ROWS_PER_WARP; i++) {
        unsigned ma0 = __ballot_sync(0xFFFFFFFFu, av0[i] > 0.5f);
        unsigned ma1 = __ballot_sync(0xFFFFFFFFu, av1[i] > 0.5f);
        unsigned mb0 = __ballot_sync(0xFFFFFFFFu, bv0[i] > 0.5f);
        unsigned mb1 = __ballot_sync(0xFFFFFFFFu, bv1[i] > 0.5f);

        const uint64_t a = (uint64_t)ma0 | ((uint64_t)(ma1 & 0x3FFFFFu) << 32);
        const uint64_t b = (uint64_t)mb0 | ((uint64_t)(mb1 & 0x3FFFFFu) << 32);

        const uint64_t lo = a * b;             // product bits [0:64)
        const uint64_t hi = __umul64hi(a, b);  // product bits [64:108)

        if (lane < 27 && rows[i] < batch) {
            unsigned nib = (lane < 16) ? (unsigned)(lo >> (lane * 4))
                                       : (unsigned)(hi >> ((lane - 16) * 4));
            uint4 v;
            v.x = ( nib        & 1u) * 0x3F800000u;
            v.y = ((nib >> 1)  & 1u) * 0x3F800000u;
            v.z = ((nib >> 2)  & 1u) * 0x3F800000u;
            v.w = ((nib >> 3)  & 1u) * 0x3F800000u;
            ((uint4*)(out + (size_t)rows[i] * 108))[lane] = v;
        }
    }
}

extern "C" void kernel_launch(void* const* d_in, const int* in_sizes, int n_in,
                              void* d_out, int out_size) {
    const float* A = (const float*)d_in[0];
    const float* B = (const float*)d_in[1];
    float* out = (float*)d_out;

    const int batch = in_sizes[0] / 54;                    // 8192 expected
    const int threads = 256;                               // 8 warps/block
    const int warpsNeeded = (batch + ROWS_PER_WARP - 1) / ROWS_PER_WARP;  // 2048
    const int blocks = (warpsNeeded + 7) / 8;              // 256 CTAs

    mul54x54_mlp_kernel<<<blocks, threads>>>(A, B, out, batch);
}